// round 4
// baseline (speedup 1.0000x reference)
#include <cuda_runtime.h>
#include <math.h>

#define NBLK 128
#define NTHR 256

#define NB 2
#define NF 32
#define ND 512
#define NH 8
#define NHD 64
#define NFF 2048
#define NL 4
#define NM 256

// ---------------- persistent device state (no allocs) ----------------
__device__ float g_K [NL][NB][NF][ND];
__device__ float g_Vo[NL][NB][NF][NH][ND];   // per-head v @ Wo_h
__device__ float g_Vt[NL][NB][NF][ND];
__device__ float g_CA[NL][NB][NF][ND];
__device__ float g_gb[NL * 3][NB][2 * ND];
__device__ float g_ppe[NF][ND];
__device__ float g_x0[NB][ND];
__device__ float g_q [NB][ND];
__device__ float g_v [NB][ND];
__device__ float g_att[NB][NH][NF];
__device__ float g_y1[NB][ND];
__device__ float g_x2[NB][ND];
__device__ float g_h [NB][NFF];
__device__ float g_y3[NB][ND];

__device__ unsigned g_barcnt = 0;
__device__ unsigned g_gen = 0;

struct Smem {
    float x[4096];
    float x2[512];
    float part[32][32];
    float red[32];
    float red2[8][32][2];
};

// ---------------- grid barrier: read-only acquire polls ----------------
__device__ __forceinline__ void gsync(unsigned& ep) {
    __syncthreads();
    ep++;
    if (threadIdx.x == 0) {
        __threadfence();                       // release my writes
        if (atomicAdd(&g_barcnt, 1u) == (unsigned)(NBLK - 1)) {
            atomicExch(&g_barcnt, 0u);
            __threadfence();
            atomicExch(&g_gen, ep);            // publish epoch
        } else {
            unsigned v;
            do {
                asm volatile("ld.acquire.gpu.global.u32 %0, [%1];"
                             : "=r"(v) : "l"(&g_gen));
            } while (v != ep);
        }
        __threadfence();                       // acquire: invalidate L1
    }
    __syncthreads();
}

// ---------------- block-wide SALN on a 512-slice (shared src/dst) ----------
__device__ __forceinline__ void blk_saln(Smem& sm, const float* G,
                                         const float* src, float* dst,
                                         const float* addv) {
    int tid = threadIdx.x;
    float a0 = src[tid], a1 = src[tid + 256];
    float s = a0 + a1, q = a0 * a0 + a1 * a1;
#pragma unroll
    for (int o = 16; o; o >>= 1) {
        s += __shfl_xor_sync(0xffffffffu, s, o);
        q += __shfl_xor_sync(0xffffffffu, q, o);
    }
    if ((tid & 31) == 0) { sm.red[tid >> 5] = s; sm.red[8 + (tid >> 5)] = q; }
    __syncthreads();
    if (tid == 0) {
        float S = 0.f, Q = 0.f;
#pragma unroll
        for (int k = 0; k < 8; k++) { S += sm.red[k]; Q += sm.red[8 + k]; }
        float mu = S * (1.f / 512.f);
        sm.red[16] = mu;
        sm.red[17] = rsqrtf(Q * (1.f / 512.f) - mu * mu + 1e-5f);
    }
    __syncthreads();
    float mu = sm.red[16], rs = sm.red[17];
    float o0 = (a0 - mu) * rs * G[tid] + G[512 + tid];
    float o1 = (a1 - mu) * rs * G[tid + 256] + G[512 + tid + 256];
    if (addv) { o0 += addv[tid]; o1 += addv[tid + 256]; }
    __syncthreads();
    dst[tid] = o0; dst[tid + 256] = o1;
    __syncthreads();
}

// ---- 32-col GEMV tile, float4 weight loads, high MLP --------------------
// W points at (row0, colbase); returns result for col = tid (tid < 32).
template <int K>
__device__ __forceinline__ float gemv32(const float* __restrict__ W, int ldw,
                                        const float* __restrict__ x, Smem& sm) {
    const int KE = K / 32;
    int tq = threadIdx.x & 7, te = threadIdx.x >> 3;
    const float* Wt = W + (size_t)(te * KE) * ldw + tq * 4;
    float a0 = 0.f, a1 = 0.f, a2 = 0.f, a3 = 0.f;
#pragma unroll 16
    for (int e = 0; e < KE; e++) {
        float4 w = *reinterpret_cast<const float4*>(Wt + (size_t)e * ldw);
        float xe = x[te * KE + e];
        a0 += xe * w.x; a1 += xe * w.y; a2 += xe * w.z; a3 += xe * w.w;
    }
    sm.part[te][tq * 4 + 0] = a0; sm.part[te][tq * 4 + 1] = a1;
    sm.part[te][tq * 4 + 2] = a2; sm.part[te][tq * 4 + 3] = a3;
    __syncthreads();
    float s = 0.f;
    if (threadIdx.x < 32) {
#pragma unroll
        for (int k = 0; k < 32; k++) s += sm.part[k][threadIdx.x];
    }
    __syncthreads();
    return s;
}

// dual-batch 32-col GEMV (precompute helper)
template <int K>
__device__ __forceinline__ void gemv2(Smem& sm, const float* xx,
                                      const float* W, int ldw,
                                      float& out0, float& out1) {
    const int KC = K / 8;
    int c = threadIdx.x & 31, r = threadIdx.x >> 5;
    const float* Wp = W + (size_t)(r * KC) * ldw + c;
    float a0 = 0.f, a1 = 0.f;
#pragma unroll 8
    for (int e = 0; e < KC; e++) {
        float w = Wp[(size_t)e * ldw];
        a0 += xx[r * KC + e] * w;
        a1 += xx[K + r * KC + e] * w;
    }
    sm.red2[r][c][0] = a0; sm.red2[r][c][1] = a1;
    __syncthreads();
    if (r == 0) {
        float s0 = 0.f, s1 = 0.f;
#pragma unroll
        for (int k = 0; k < 8; k++) { s0 += sm.red2[k][c][0]; s1 += sm.red2[k][c][1]; }
        out0 = s0; out1 = s1;
    }
    __syncthreads();
}

// ---------------------------------------------------------------------------
__global__ __launch_bounds__(NTHR) void mega(
    const float* __restrict__ content, const float* __restrict__ style,
    const float* __restrict__ init_st,
    const float* __restrict__ motion_W, const float* __restrict__ motion_b,
    const float* __restrict__ motionr_W, const float* __restrict__ motionr_b,
    const float* __restrict__ sa_Wq, const float* __restrict__ sa_bq,
    const float* __restrict__ sa_Wk, const float* __restrict__ sa_bk,
    const float* __restrict__ sa_Wv, const float* __restrict__ sa_bv,
    const float* __restrict__ sa_Wo, const float* __restrict__ sa_bo,
    const float* __restrict__ ca_Wv, const float* __restrict__ ca_bv,
    const float* __restrict__ ca_Wo, const float* __restrict__ ca_bo,
    const float* __restrict__ ff_W1, const float* __restrict__ ff_b1,
    const float* __restrict__ ff_W2, const float* __restrict__ ff_b2,
    const float* __restrict__ saln_W, const float* __restrict__ saln_b,
    float* __restrict__ outp)
{
    __shared__ Smem sm;
    const int blk = blockIdx.x, tid = threadIdx.x;
    unsigned ep;
    asm volatile("ld.acquire.gpu.global.u32 %0, [%1];" : "=r"(ep) : "l"(&g_gen));

    // ================= P0: PPE + SALN gamma/beta + Vt = content@Wv+bv ========
    {
        int idx = blk * NTHR + tid;
        if (idx < NF * ND) {
            int f = idx >> 9, d = idx & 511;
            float divv = expf((float)(d & ~1) * (-9.210340371976184f / 512.0f));
            float a = (float)(f % 30) * divv;
            g_ppe[f][d] = (d & 1) ? cosf(a) : sinf(a);
        }
    }
    for (int t = blk; t < 384; t += NBLK) {     // 12 ls * 32 coltiles
        int ls = t >> 5, colbase = (t & 31) * 32;
        for (int u = tid; u < 1024; u += NTHR) sm.x[u] = style[u];
        __syncthreads();
        float o0, o1;
        gemv2<512>(sm, sm.x, saln_W + (size_t)ls * 512 * 1024 + colbase, 1024, o0, o1);
        if (tid < 32) {
            float bb = saln_b[ls * 1024 + colbase + tid];
            g_gb[ls][0][colbase + tid] = o0 + bb;
            g_gb[ls][1][colbase + tid] = o1 + bb;
        }
        __syncthreads();
    }
    for (int t = blk; t < 512; t += NBLK) {     // 4 l * 16 coltiles * 8 rowgroups
        int l = t >> 7, colt = (t >> 3) & 15, rg = t & 7;
        int colbase = colt * 32;
        int c = tid & 31, r = tid >> 5;
        for (int u = tid; u < 4096; u += NTHR)
            sm.x[u] = content[(size_t)(rg * 8) * 512 + u];
        __syncthreads();
        const float* Wp = ca_Wv + (size_t)l * 512 * 512 + (size_t)(r * 64) * 512 + colbase + c;
        float acc[8];
#pragma unroll
        for (int rr = 0; rr < 8; rr++) acc[rr] = 0.f;
#pragma unroll 8
        for (int e = 0; e < 64; e++) {
            float w = Wp[(size_t)e * 512];
#pragma unroll
            for (int rr = 0; rr < 8; rr++) acc[rr] += sm.x[rr * 512 + r * 64 + e] * w;
        }
        for (int rr = 0; rr < 8; rr++) {
            sm.red2[r][c][0] = acc[rr];
            __syncthreads();
            if (r == 0) {
                float s = 0.f;
#pragma unroll
                for (int k = 0; k < 8; k++) s += sm.red2[k][c][0];
                int row = rg * 8 + rr;
                g_Vt[l][row >> 5][row & 31][colbase + c] = s + ca_bv[l * 512 + colbase + c];
            }
            __syncthreads();
        }
    }
    gsync(ep);

    // ================= P1: CA = Vt@Wo+bo  and  emb0 ==========================
    for (int t = blk; t < 512; t += NBLK) {
        int l = t >> 7, colt = (t >> 3) & 15, rg = t & 7;
        int colbase = colt * 32;
        int c = tid & 31, r = tid >> 5;
        const float* vt = &g_Vt[l][0][0][0];
        for (int u = tid; u < 4096; u += NTHR)
            sm.x[u] = vt[(size_t)(rg * 8) * 512 + u];
        __syncthreads();
        const float* Wp = ca_Wo + (size_t)l * 512 * 512 + (size_t)(r * 64) * 512 + colbase + c;
        float acc[8];
#pragma unroll
        for (int rr = 0; rr < 8; rr++) acc[rr] = 0.f;
#pragma unroll 8
        for (int e = 0; e < 64; e++) {
            float w = Wp[(size_t)e * 512];
#pragma unroll
            for (int rr = 0; rr < 8; rr++) acc[rr] += sm.x[rr * 512 + r * 64 + e] * w;
        }
        for (int rr = 0; rr < 8; rr++) {
            sm.red2[r][c][0] = acc[rr];
            __syncthreads();
            if (r == 0) {
                float s = 0.f;
#pragma unroll
                for (int k = 0; k < 8; k++) s += sm.red2[k][c][0];
                int row = rg * 8 + rr;
                g_CA[l][row >> 5][row & 31][colbase + c] = s + ca_bo[l * 512 + colbase + c];
            }
            __syncthreads();
        }
    }
    if (blk < 16) {                              // emb0: x0 = init@Wm + bm + ppe[0]
        for (int u = tid; u < 512; u += NTHR) sm.x[u] = init_st[u];
        __syncthreads();
        float o0, o1;
        gemv2<256>(sm, sm.x, motion_W + blk * 32, 512, o0, o1);
        if (tid < 32) {
            int col = blk * 32 + tid;
            float ex = motion_b[col] + g_ppe[0][col];
            g_x0[0][col] = o0 + ex;
            g_x0[1][col] = o1 + ex;
        }
    }
    gsync(ep);

    // ================= autoregressive decode =================================
    for (int i = 0; i < NF; i++) {
        for (int l = 0; l < NL; l++) {
            // ---- A: (saln3 of prev layer, redundant) + q/k/v GEMVs ----
            if (blk < 96) {
                int b = blk & 1, t = blk >> 1;        // t < 48
                int which = t >> 4, coltile = t & 15;
                if (l == 0) {
                    for (int u = tid; u < 512; u += NTHR) sm.x[u] = g_x0[b][u];
                    __syncthreads();
                } else {
                    for (int u = tid; u < 512; u += NTHR) sm.x[u] = g_y3[b][u];
                    __syncthreads();
                    blk_saln(sm, g_gb[(l - 1) * 3 + 2][b], sm.x, sm.x, 0);
                    if (t == 0) {                     // blocks 0,1 refresh g_x0
                        g_x0[b][tid] = sm.x[tid];
                        g_x0[b][tid + 256] = sm.x[tid + 256];
                    }
                }
                const float* W = (which == 0 ? sa_Wq : which == 1 ? sa_Wk : sa_Wv)
                               + (size_t)l * 512 * 512 + coltile * 32;
                float s = gemv32<512>(W, 512, sm.x, sm);
                if (tid < 32) {
                    int col = coltile * 32 + tid;
                    const float* bias = which == 0 ? sa_bq : which == 1 ? sa_bk : sa_bv;
                    s += bias[l * 512 + col];
                    if (which == 0)      g_q[b][col] = s;
                    else if (which == 1) g_K[l][b][i][col] = s;
                    else                 g_v[b][col] = s;
                }
            }
            gsync(ep);

            // ---- B: Vo[h] = v_h @ Wo_h (all blocks) + scores (blocks 126/127) ----
#pragma unroll
            for (int p = 0; p < 2; p++) {
                int tt = blk + NBLK * p;              // 256 tiles
                int b = tt >> 7, h = (tt >> 4) & 7, coltile = tt & 15;
                if (tid < 64) sm.x[tid] = g_v[b][h * 64 + tid];
                __syncthreads();
                float s = gemv32<64>(sa_Wo + (size_t)l * 512 * 512
                                     + (size_t)(h * 64) * 512 + coltile * 32,
                                     512, sm.x, sm);
                if (tid < 32) g_Vo[l][b][i][h][coltile * 32 + tid] = s;
                __syncthreads();
            }
            if (blk >= 126) {
                int b = blk - 126;
                for (int u = tid; u < 512; u += NTHR) sm.x2[u] = g_q[b][u];
                __syncthreads();
                int h = tid >> 5, j = tid & 31;
                float sc = -1e30f;
                if (j <= i) {
                    const float* kp = &g_K[l][b][j][h * 64];
                    float d = 0.f;
#pragma unroll
                    for (int e = 0; e < 64; e++) d += sm.x2[h * 64 + e] * kp[e];
                    sc = d * 0.125f - exp2f(-(float)(h + 1)) * (float)((i - j) / 30);
                }
                float mx = sc;
#pragma unroll
                for (int o = 16; o; o >>= 1) mx = fmaxf(mx, __shfl_xor_sync(0xffffffffu, mx, o));
                float ev = (j <= i) ? expf(sc - mx) : 0.f;
                float smm = ev;
#pragma unroll
                for (int o = 16; o; o >>= 1) smm += __shfl_xor_sync(0xffffffffu, smm, o);
                g_att[b][h][j] = ev / smm;
            }
            gsync(ep);

            // ---- C: y1 = sum att*Vo + bo + x0 ----
            if (blk < 32) {
                int b = blk & 1, dbase = (blk >> 1) * 32;
                for (int u = tid; u < 256; u += NTHR) sm.x2[u] = (&g_att[b][0][0])[u];
                __syncthreads();
                int rr = tid >> 5, cc = tid & 31;
                int d = dbase + cc;
                int M = (i + 1) * 8;
                float a = 0.f;
                for (int m = rr; m < M; m += 8) {
                    int j = m >> 3, h = m & 7;
                    a += sm.x2[h * 32 + j] * g_Vo[l][b][j][h][d];
                }
                sm.part[rr][cc] = a;
                __syncthreads();
                if (tid < 32) {
                    float s = 0.f;
#pragma unroll
                    for (int k = 0; k < 8; k++) s += sm.part[k][tid];
                    int col = dbase + tid;
                    g_y1[b][col] = s + sa_bo[l * 512 + col] + g_x0[b][col];
                }
            }
            gsync(ep);

            // ---- D: saln1+CA+saln2 (redundant) + FF1 (all 128 blocks) ----
            {
                int b = blk & 1;
                for (int u = tid; u < 512; u += NTHR) sm.x[u] = g_y1[b][u];
                __syncthreads();
                blk_saln(sm, g_gb[l * 3 + 0][b], sm.x, sm.x, &g_CA[l][b][i][0]);
                blk_saln(sm, g_gb[l * 3 + 1][b], sm.x, sm.x, 0);
                if (blk < 2) {
                    g_x2[b][tid] = sm.x[tid];
                    g_x2[b][tid + 256] = sm.x[tid + 256];
                }
                int colbase = (blk >> 1) * 32;        // 64 coltiles x 32 = 2048
                float s = gemv32<512>(ff_W1 + (size_t)l * 512 * 2048 + colbase,
                                      2048, sm.x, sm);
                if (tid < 32) {
                    int col = colbase + tid;
                    g_h[b][col] = fmaxf(s + ff_b1[l * 2048 + col], 0.f);
                }
            }
            gsync(ep);

            // ---- E: y3 = h@W2 + b2 + x2 ----
            if (blk < 32) {
                int b = blk & 1, colbase = (blk >> 1) * 32;
                for (int u = tid; u < 512; u += NTHR)
                    reinterpret_cast<float4*>(sm.x)[u] =
                        reinterpret_cast<const float4*>(&g_h[b][0])[u];
                __syncthreads();
                float s = gemv32<2048>(ff_W2 + (size_t)l * 2048 * 512 + colbase,
                                       512, sm.x, sm);
                if (tid < 32) {
                    int col = colbase + tid;
                    g_y3[b][col] = s + ff_b2[l * 512 + col] + g_x2[b][col];
                }
            }
            gsync(ep);
        } // layers

        // ---- OUT: row i = saln3(y3) @ motionr_W + br ----
        if (blk < 16) {
            int b = blk & 1, colbase = (blk >> 1) * 32;   // 8 tiles -> 256 cols
            for (int u = tid; u < 512; u += NTHR) sm.x[u] = g_y3[b][u];
            __syncthreads();
            blk_saln(sm, g_gb[3 * 3 + 2][b], sm.x, sm.x, 0);
            float s = gemv32<512>(motionr_W + colbase, 256, sm.x, sm);
            if (tid < 32) {
                int col = colbase + tid;
                outp[(size_t)b * NF * NM + (size_t)i * NM + col] = s + motionr_b[col];
            }
        }
        gsync(ep);

        // ---- EMB: x0 = out_row @ motion_W + bm + ppe[i+1] ----
        if (i < NF - 1) {
            if (blk < 32) {
                int b = blk & 1, colbase = (blk >> 1) * 32;  // 16 tiles -> 512 cols
                for (int u = tid; u < 256; u += NTHR)
                    sm.x[u] = outp[(size_t)b * NF * NM + (size_t)i * NM + u];
                __syncthreads();
                float s = gemv32<256>(motion_W + colbase, 512, sm.x, sm);
                if (tid < 32) {
                    int col = colbase + tid;
                    g_x0[b][col] = s + motion_b[col] + g_ppe[i + 1][col];
                }
            }
            gsync(ep);
        }
    } // steps
}

// ---------------------------------------------------------------------------
extern "C" void kernel_launch(void* const* d_in, const int* in_sizes, int n_in,
                              void* d_out, int out_size) {
    mega<<<NBLK, NTHR>>>(
        (const float*)d_in[0],  (const float*)d_in[1],  (const float*)d_in[2],
        (const float*)d_in[3],  (const float*)d_in[4],  (const float*)d_in[5],
        (const float*)d_in[6],
        (const float*)d_in[7],  (const float*)d_in[8],  (const float*)d_in[9],
        (const float*)d_in[10], (const float*)d_in[11], (const float*)d_in[12],
        (const float*)d_in[13], (const float*)d_in[14],
        /* ca_Wq/bq/Wk/bk (15-18) unused: one-hot cross-attn softmax */
        (const float*)d_in[19], (const float*)d_in[20], (const float*)d_in[21],
        (const float*)d_in[22],
        (const float*)d_in[23], (const float*)d_in[24], (const float*)d_in[25],
        (const float*)d_in[26],
        (const float*)d_in[27], (const float*)d_in[28],
        (float*)d_out);
    (void)in_sizes; (void)n_in; (void)out_size;
}

// round 5
// speedup vs baseline: 1.1176x; 1.1176x over previous
#include <cuda_runtime.h>
#include <math.h>

#define NBLK 64
#define NTHR 256

#define NB 2
#define NF 32
#define ND 512
#define NH 8
#define NHD 64
#define NFF 2048
#define NL 4
#define NM 256

// ---------------- persistent device state (no allocs) ----------------
__device__ float g_K [NL][NB][NF][ND];
__device__ float g_Vo[NL][NB][NF][NH][ND];   // per-head v @ Wo_h
__device__ float g_Vt[NL][NB][NF][ND];
__device__ float g_CA[NL][NB][NF][ND];
__device__ float g_gb[NL * 3][NB][2 * ND];
__device__ float g_ppe[NF][ND];
__device__ float g_x0[NB][ND];
__device__ float g_q [NB][ND];
__device__ float g_v [NB][ND];
__device__ float g_att[NB][NH][NF];
__device__ float g_y1[NB][ND];
__device__ float g_x2[NB][ND];
__device__ float g_h [NB][NFF];
__device__ float g_y3[NB][ND];

// barrier state: one padded cache line per block (no RMW contention)
struct Flag { unsigned v; unsigned pad[31]; };
__device__ Flag g_flag[NBLK];
__device__ unsigned g_gen2 = 0;

struct Smem {
    float x[4096];
    float x2[512];
    float part[2048];
    float red[32];
    float red2[8][32][2];
};

__device__ __forceinline__ unsigned ld_acq(const unsigned* p) {
    unsigned v;
    asm volatile("ld.acquire.gpu.global.u32 %0, [%1];" : "=r"(v) : "l"(p));
    return v;
}
__device__ __forceinline__ void st_rel(unsigned* p, unsigned v) {
    asm volatile("st.release.gpu.global.u32 [%0], %1;" :: "l"(p), "r"(v));
}

// ---------------- grid barrier: per-block flags, parallel aggregation -------
__device__ __forceinline__ void gsync(unsigned& ep) {
    __syncthreads();
    ep++;
    if (blockIdx.x == 0) {
        if (threadIdx.x > 0 && threadIdx.x < NBLK) {
            while ((int)(ld_acq(&g_flag[threadIdx.x].v) - ep) < 0) {}
        }
        __syncthreads();                       // all flags acquired
        if (threadIdx.x == 0) st_rel(&g_gen2, ep);
    } else {
        if (threadIdx.x == 0) {
            st_rel(&g_flag[blockIdx.x].v, ep);
            while ((int)(ld_acq(&g_gen2) - ep) < 0) {}
        }
        __syncthreads();
    }
    __syncthreads();
}

// ---------------- block-wide SALN on a 512-slice (shared src/dst) ----------
__device__ __forceinline__ void blk_saln(Smem& sm, const float* G,
                                         const float* src, float* dst,
                                         const float* addv) {
    int tid = threadIdx.x;
    float a0 = src[tid], a1 = src[tid + 256];
    float s = a0 + a1, q = a0 * a0 + a1 * a1;
#pragma unroll
    for (int o = 16; o; o >>= 1) {
        s += __shfl_xor_sync(0xffffffffu, s, o);
        q += __shfl_xor_sync(0xffffffffu, q, o);
    }
    if ((tid & 31) == 0) { sm.red[tid >> 5] = s; sm.red[8 + (tid >> 5)] = q; }
    __syncthreads();
    if (tid == 0) {
        float S = 0.f, Q = 0.f;
#pragma unroll
        for (int k = 0; k < 8; k++) { S += sm.red[k]; Q += sm.red[8 + k]; }
        float mu = S * (1.f / 512.f);
        sm.red[16] = mu;
        sm.red[17] = rsqrtf(Q * (1.f / 512.f) - mu * mu + 1e-5f);
    }
    __syncthreads();
    float mu = sm.red[16], rs = sm.red[17];
    float o0 = (a0 - mu) * rs * G[tid] + G[512 + tid];
    float o1 = (a1 - mu) * rs * G[tid + 256] + G[512 + tid + 256];
    if (addv) { o0 += addv[tid]; o1 += addv[tid + 256]; }
    __syncthreads();
    dst[tid] = o0; dst[tid + 256] = o1;
    __syncthreads();
}

// ---- dual-batch NC-col GEMV tile with float4 weight loads -----------------
// One float4 weight load feeds both batch rows. Results valid for tid < NC.
template <int NC, int K>
__device__ __forceinline__ void gemvx2(const float* __restrict__ W, int ldw,
                                       const float* __restrict__ x0,
                                       const float* __restrict__ x1,
                                       Smem& sm, float& o0, float& o1) {
    const int QP = NC / 4;             // float4 tiles per row
    const int G  = NTHR / QP;          // K-groups
    const int KE = K / G;
    int tq = threadIdx.x % QP, te = threadIdx.x / QP;
    const float* Wt = W + (size_t)(te * KE) * ldw + tq * 4;
    float a0 = 0.f, a1 = 0.f, a2 = 0.f, a3 = 0.f;
    float b0 = 0.f, b1 = 0.f, b2 = 0.f, b3 = 0.f;
#pragma unroll 8
    for (int e = 0; e < KE; e++) {
        float4 w = *reinterpret_cast<const float4*>(Wt + (size_t)e * ldw);
        float xe0 = x0[te * KE + e], xe1 = x1[te * KE + e];
        a0 += xe0 * w.x; a1 += xe0 * w.y; a2 += xe0 * w.z; a3 += xe0 * w.w;
        b0 += xe1 * w.x; b1 += xe1 * w.y; b2 += xe1 * w.z; b3 += xe1 * w.w;
    }
    float* P = sm.part + te * (2 * NC) + tq * 4;
    P[0] = a0; P[1] = a1; P[2] = a2; P[3] = a3;
    P[NC + 0] = b0; P[NC + 1] = b1; P[NC + 2] = b2; P[NC + 3] = b3;
    __syncthreads();
    o0 = 0.f; o1 = 0.f;
    if (threadIdx.x < NC) {
#pragma unroll 8
        for (int g = 0; g < G; g++) {
            o0 += sm.part[g * (2 * NC) + threadIdx.x];
            o1 += sm.part[g * (2 * NC) + NC + threadIdx.x];
        }
    }
    __syncthreads();
}

// dual-batch 32-col GEMV (precompute helper, scalar loads)
template <int K>
__device__ __forceinline__ void gemv2(Smem& sm, const float* xx,
                                      const float* W, int ldw,
                                      float& out0, float& out1) {
    const int KC = K / 8;
    int c = threadIdx.x & 31, r = threadIdx.x >> 5;
    const float* Wp = W + (size_t)(r * KC) * ldw + c;
    float a0 = 0.f, a1 = 0.f;
#pragma unroll 8
    for (int e = 0; e < KC; e++) {
        float w = Wp[(size_t)e * ldw];
        a0 += xx[r * KC + e] * w;
        a1 += xx[K + r * KC + e] * w;
    }
    sm.red2[r][c][0] = a0; sm.red2[r][c][1] = a1;
    __syncthreads();
    if (r == 0) {
        float s0 = 0.f, s1 = 0.f;
#pragma unroll
        for (int k = 0; k < 8; k++) { s0 += sm.red2[k][c][0]; s1 += sm.red2[k][c][1]; }
        out0 = s0; out1 = s1;
    }
    __syncthreads();
}

// ---------------------------------------------------------------------------
__global__ __launch_bounds__(NTHR) void mega(
    const float* __restrict__ content, const float* __restrict__ style,
    const float* __restrict__ init_st,
    const float* __restrict__ motion_W, const float* __restrict__ motion_b,
    const float* __restrict__ motionr_W, const float* __restrict__ motionr_b,
    const float* __restrict__ sa_Wq, const float* __restrict__ sa_bq,
    const float* __restrict__ sa_Wk, const float* __restrict__ sa_bk,
    const float* __restrict__ sa_Wv, const float* __restrict__ sa_bv,
    const float* __restrict__ sa_Wo, const float* __restrict__ sa_bo,
    const float* __restrict__ ca_Wv, const float* __restrict__ ca_bv,
    const float* __restrict__ ca_Wo, const float* __restrict__ ca_bo,
    const float* __restrict__ ff_W1, const float* __restrict__ ff_b1,
    const float* __restrict__ ff_W2, const float* __restrict__ ff_b2,
    const float* __restrict__ saln_W, const float* __restrict__ saln_b,
    float* __restrict__ outp)
{
    __shared__ Smem sm;
    const int blk = blockIdx.x, tid = threadIdx.x;
    unsigned ep = ld_acq(&g_gen2);

    // ================= P0: PPE + SALN gamma/beta + Vt = content@Wv+bv ========
    {
        int idx = blk * NTHR + tid;            // exactly NF*ND
        int f = idx >> 9, d = idx & 511;
        float divv = expf((float)(d & ~1) * (-9.210340371976184f / 512.0f));
        float a = (float)(f % 30) * divv;
        g_ppe[f][d] = (d & 1) ? cosf(a) : sinf(a);
    }
    for (int t = blk; t < 384; t += NBLK) {    // 12 ls * 32 coltiles
        int ls = t >> 5, colbase = (t & 31) * 32;
        for (int u = tid; u < 1024; u += NTHR) sm.x[u] = style[u];
        __syncthreads();
        float o0, o1;
        gemv2<512>(sm, sm.x, saln_W + (size_t)ls * 512 * 1024 + colbase, 1024, o0, o1);
        if (tid < 32) {
            float bb = saln_b[ls * 1024 + colbase + tid];
            g_gb[ls][0][colbase + tid] = o0 + bb;
            g_gb[ls][1][colbase + tid] = o1 + bb;
        }
        __syncthreads();
    }
    for (int t = blk; t < 512; t += NBLK) {    // 4 l * 16 coltiles * 8 rowgroups
        int l = t >> 7, colt = (t >> 3) & 15, rg = t & 7;
        int colbase = colt * 32;
        int c = tid & 31, r = tid >> 5;
        for (int u = tid; u < 4096; u += NTHR)
            sm.x[u] = content[(size_t)(rg * 8) * 512 + u];
        __syncthreads();
        const float* Wp = ca_Wv + (size_t)l * 512 * 512 + (size_t)(r * 64) * 512 + colbase + c;
        float acc[8];
#pragma unroll
        for (int rr = 0; rr < 8; rr++) acc[rr] = 0.f;
#pragma unroll 8
        for (int e = 0; e < 64; e++) {
            float w = Wp[(size_t)e * 512];
#pragma unroll
            for (int rr = 0; rr < 8; rr++) acc[rr] += sm.x[rr * 512 + r * 64 + e] * w;
        }
        for (int rr = 0; rr < 8; rr++) {
            sm.red2[r][c][0] = acc[rr];
            __syncthreads();
            if (r == 0) {
                float s = 0.f;
#pragma unroll
                for (int k = 0; k < 8; k++) s += sm.red2[k][c][0];
                int row = rg * 8 + rr;
                g_Vt[l][row >> 5][row & 31][colbase + c] = s + ca_bv[l * 512 + colbase + c];
            }
            __syncthreads();
        }
    }
    gsync(ep);

    // ================= P1: CA = Vt@Wo+bo  and  emb0 ==========================
    for (int t = blk; t < 512; t += NBLK) {
        int l = t >> 7, colt = (t >> 3) & 15, rg = t & 7;
        int colbase = colt * 32;
        int c = tid & 31, r = tid >> 5;
        const float* vt = &g_Vt[l][0][0][0];
        for (int u = tid; u < 4096; u += NTHR)
            sm.x[u] = vt[(size_t)(rg * 8) * 512 + u];
        __syncthreads();
        const float* Wp = ca_Wo + (size_t)l * 512 * 512 + (size_t)(r * 64) * 512 + colbase + c;
        float acc[8];
#pragma unroll
        for (int rr = 0; rr < 8; rr++) acc[rr] = 0.f;
#pragma unroll 8
        for (int e = 0; e < 64; e++) {
            float w = Wp[(size_t)e * 512];
#pragma unroll
            for (int rr = 0; rr < 8; rr++) acc[rr] += sm.x[rr * 512 + r * 64 + e] * w;
        }
        for (int rr = 0; rr < 8; rr++) {
            sm.red2[r][c][0] = acc[rr];
            __syncthreads();
            if (r == 0) {
                float s = 0.f;
#pragma unroll
                for (int k = 0; k < 8; k++) s += sm.red2[k][c][0];
                int row = rg * 8 + rr;
                g_CA[l][row >> 5][row & 31][colbase + c] = s + ca_bo[l * 512 + colbase + c];
            }
            __syncthreads();
        }
    }
    if (blk < 16) {                            // emb0: x0 = init@Wm + bm + ppe[0]
        for (int u = tid; u < 512; u += NTHR) sm.x[u] = init_st[u];
        __syncthreads();
        float o0, o1;
        gemv2<256>(sm, sm.x, motion_W + blk * 32, 512, o0, o1);
        if (tid < 32) {
            int col = blk * 32 + tid;
            float ex = motion_b[col] + g_ppe[0][col];
            g_x0[0][col] = o0 + ex;
            g_x0[1][col] = o1 + ex;
        }
    }
    gsync(ep);

    // ================= autoregressive decode =================================
    for (int i = 0; i < NF; i++) {
        for (int l = 0; l < NL; l++) {
            // ---- A: (saln3 of prev layer, redundant) + q/k/v dual-batch GEMVs
            if (blk < 48) {
                int which = blk >> 4, ct = blk & 15;
                if (l == 0) {
                    for (int u = tid; u < 1024; u += NTHR) sm.x[u] = ((const float*)g_x0)[u];
                    __syncthreads();
                } else {
                    for (int u = tid; u < 1024; u += NTHR) sm.x[u] = ((const float*)g_y3)[u];
                    __syncthreads();
                    blk_saln(sm, g_gb[(l - 1) * 3 + 2][0], sm.x, sm.x, 0);
                    blk_saln(sm, g_gb[(l - 1) * 3 + 2][1], sm.x + 512, sm.x + 512, 0);
                    if (blk == 0) {
                        float* x0f = (float*)g_x0;
                        x0f[tid] = sm.x[tid];             x0f[tid + 256] = sm.x[tid + 256];
                        x0f[tid + 512] = sm.x[tid + 512]; x0f[tid + 768] = sm.x[tid + 768];
                    }
                }
                const float* W = (which == 0 ? sa_Wq : which == 1 ? sa_Wk : sa_Wv)
                               + (size_t)l * 512 * 512 + ct * 32;
                float o0, o1;
                gemvx2<32, 512>(W, 512, sm.x, sm.x + 512, sm, o0, o1);
                if (tid < 32) {
                    int col = ct * 32 + tid;
                    const float* bias = which == 0 ? sa_bq : which == 1 ? sa_bk : sa_bv;
                    float bb = bias[l * 512 + col];
                    o0 += bb; o1 += bb;
                    if (which == 0)      { g_q[0][col] = o0;       g_q[1][col] = o1; }
                    else if (which == 1) { g_K[l][0][i][col] = o0; g_K[l][1][i][col] = o1; }
                    else                 { g_v[0][col] = o0;       g_v[1][col] = o1; }
                }
            }
            gsync(ep);

            // ---- B: Vo[b][h] = v_h @ Wo_h (dual-batch, 128 tiles) + scores ----
#pragma unroll
            for (int p = 0; p < 2; p++) {
                int u = blk + NBLK * p;                 // 0..127
                int h = u >> 4, ct = u & 15;
                __syncthreads();
                if (tid < 64)       sm.x2[tid] = g_v[0][h * 64 + tid];
                else if (tid < 128) sm.x2[tid] = g_v[1][h * 64 + (tid - 64)];
                __syncthreads();
                float o0, o1;
                gemvx2<32, 64>(sa_Wo + (size_t)l * 512 * 512 + (size_t)(h * 64) * 512 + ct * 32,
                               512, sm.x2, sm.x2 + 64, sm, o0, o1);
                if (tid < 32) {
                    int col = ct * 32 + tid;
                    g_Vo[l][0][i][h][col] = o0;
                    g_Vo[l][1][i][h][col] = o1;
                }
            }
            if (blk >= 62) {                            // scores+softmax, b = blk-62
                int b = blk - 62;
                __syncthreads();
                for (int u = tid; u < 512; u += NTHR) sm.x[u] = g_q[b][u];
                __syncthreads();
                int h = tid >> 5, j = tid & 31;
                float sc = -1e30f;
                if (j <= i) {
                    const float* kp = &g_K[l][b][j][h * 64];
                    float d = 0.f;
#pragma unroll
                    for (int e = 0; e < 64; e++) d += sm.x[h * 64 + e] * kp[e];
                    sc = d * 0.125f - exp2f(-(float)(h + 1)) * (float)((i - j) / 30);
                }
                float mx = sc;
#pragma unroll
                for (int o = 16; o; o >>= 1) mx = fmaxf(mx, __shfl_xor_sync(0xffffffffu, mx, o));
                float ev = (j <= i) ? expf(sc - mx) : 0.f;
                float smm = ev;
#pragma unroll
                for (int o = 16; o; o >>= 1) smm += __shfl_xor_sync(0xffffffffu, smm, o);
                g_att[b][h][j] = ev / smm;
            }
            gsync(ep);

            // ---- C: y1 = sum att*Vo + bo + x0 ----
            if (blk < 32) {
                int b = blk & 1, dbase = (blk >> 1) * 32;
                for (int u = tid; u < 256; u += NTHR) sm.x2[u] = (&g_att[b][0][0])[u];
                __syncthreads();
                int rr = tid >> 5, cc = tid & 31;
                int d = dbase + cc;
                int M = (i + 1) * 8;
                float a = 0.f;
                for (int m = rr; m < M; m += 8) {
                    int j = m >> 3, h = m & 7;
                    a += sm.x2[h * 32 + j] * g_Vo[l][b][j][h][d];
                }
                sm.part[rr * 32 + cc] = a;
                __syncthreads();
                if (tid < 32) {
                    float s = 0.f;
#pragma unroll
                    for (int k = 0; k < 8; k++) s += sm.part[k * 32 + tid];
                    int col = dbase + tid;
                    g_y1[b][col] = s + sa_bo[l * 512 + col] + g_x0[b][col];
                }
            }
            gsync(ep);

            // ---- D: saln1+CA+saln2 (redundant) + FF1 (all 64 blocks, dual) ----
            {
                for (int u = tid; u < 1024; u += NTHR) sm.x[u] = ((const float*)g_y1)[u];
                __syncthreads();
                blk_saln(sm, g_gb[l * 3 + 0][0], sm.x, sm.x, &g_CA[l][0][i][0]);
                blk_saln(sm, g_gb[l * 3 + 1][0], sm.x, sm.x, 0);
                blk_saln(sm, g_gb[l * 3 + 0][1], sm.x + 512, sm.x + 512, &g_CA[l][1][i][0]);
                blk_saln(sm, g_gb[l * 3 + 1][1], sm.x + 512, sm.x + 512, 0);
                if (blk == 0) {
                    float* x2f = (float*)g_x2;
                    x2f[tid] = sm.x[tid];             x2f[tid + 256] = sm.x[tid + 256];
                    x2f[tid + 512] = sm.x[tid + 512]; x2f[tid + 768] = sm.x[tid + 768];
                }
                int colbase = blk * 32;                 // 64 tiles x 32 = 2048
                float o0, o1;
                gemvx2<32, 512>(ff_W1 + (size_t)l * 512 * 2048 + colbase, 2048,
                                sm.x, sm.x + 512, sm, o0, o1);
                if (tid < 32) {
                    int col = colbase + tid;
                    float bb = ff_b1[l * 2048 + col];
                    g_h[0][col] = fmaxf(o0 + bb, 0.f);
                    g_h[1][col] = fmaxf(o1 + bb, 0.f);
                }
            }
            gsync(ep);

            // ---- E: y3 = h@W2 + b2 + x2 (32 blocks x 16 cols, dual) ----
            if (blk < 32) {
                for (int u = tid; u < 1024; u += NTHR)
                    reinterpret_cast<float4*>(sm.x)[u] =
                        reinterpret_cast<const float4*>(&g_h[0][0])[u];
                __syncthreads();
                int colbase = blk * 16;
                float o0, o1;
                gemvx2<16, 2048>(ff_W2 + (size_t)l * 2048 * 512 + colbase, 512,
                                 sm.x, sm.x + 2048, sm, o0, o1);
                if (tid < 16) {
                    int col = colbase + tid;
                    float bb = ff_b2[l * 512 + col];
                    g_y3[0][col] = o0 + bb + g_x2[0][col];
                    g_y3[1][col] = o1 + bb + g_x2[1][col];
                }
            }
            gsync(ep);
        } // layers

        // ---- OUT: row i = saln3(y3) @ motionr_W + br (8 blocks, dual) ----
        if (blk < 8) {
            for (int u = tid; u < 1024; u += NTHR) sm.x[u] = ((const float*)g_y3)[u];
            __syncthreads();
            blk_saln(sm, g_gb[3 * 3 + 2][0], sm.x, sm.x, 0);
            blk_saln(sm, g_gb[3 * 3 + 2][1], sm.x + 512, sm.x + 512, 0);
            int colbase = blk * 32;                     // 8 x 32 = 256
            float o0, o1;
            gemvx2<32, 512>(motionr_W + colbase, 256, sm.x, sm.x + 512, sm, o0, o1);
            if (tid < 32) {
                int col = colbase + tid;
                float bb = motionr_b[col];
                outp[(size_t)0 * NF * NM + (size_t)i * NM + col] = o0 + bb;
                outp[(size_t)1 * NF * NM + (size_t)i * NM + col] = o1 + bb;
            }
        }
        gsync(ep);

        // ---- EMB: x0 = out_row @ motion_W + bm + ppe[i+1] (16 blocks, dual) --
        if (i < NF - 1) {
            if (blk < 16) {
                for (int u = tid; u < 512; u += NTHR) {
                    int b = u >> 8, e = u & 255;
                    sm.x[u] = outp[(size_t)b * NF * NM + (size_t)i * NM + e];
                }
                __syncthreads();
                int colbase = blk * 32;                 // 16 x 32 = 512
                float o0, o1;
                gemvx2<32, 256>(motion_W + colbase, 512, sm.x, sm.x + 256, sm, o0, o1);
                if (tid < 32) {
                    int col = colbase + tid;
                    float ex = motion_b[col] + g_ppe[i + 1][col];
                    g_x0[0][col] = o0 + ex;
                    g_x0[1][col] = o1 + ex;
                }
            }
            gsync(ep);
        }
    } // steps
}

// ---------------------------------------------------------------------------
extern "C" void kernel_launch(void* const* d_in, const int* in_sizes, int n_in,
                              void* d_out, int out_size) {
    mega<<<NBLK, NTHR>>>(
        (const float*)d_in[0],  (const float*)d_in[1],  (const float*)d_in[2],
        (const float*)d_in[3],  (const float*)d_in[4],  (const float*)d_in[5],
        (const float*)d_in[6],
        (const float*)d_in[7],  (const float*)d_in[8],  (const float*)d_in[9],
        (const float*)d_in[10], (const float*)d_in[11], (const float*)d_in[12],
        (const float*)d_in[13], (const float*)d_in[14],
        /* ca_Wq/bq/Wk/bk (15-18) unused: one-hot cross-attn softmax */
        (const float*)d_in[19], (const float*)d_in[20], (const float*)d_in[21],
        (const float*)d_in[22],
        (const float*)d_in[23], (const float*)d_in[24], (const float*)d_in[25],
        (const float*)d_in[26],
        (const float*)d_in[27], (const float*)d_in[28],
        (float*)d_out);
    (void)in_sizes; (void)n_in; (void)out_size;
}